// round 8
// baseline (speedup 1.0000x reference)
#include <cuda_runtime.h>

#define B   8
#define C   1024
#define HW  4096
#define K   16

// Scratch (no allocations allowed) — fully rewritten every launch.
__device__ float g_num[B * K * C];      // masked class sums
__device__ float g_protoN[B * K * C];   // prototypes / (count * ||proto||)
__device__ int   g_counts[B * (K + 1)]; // per-class pixel counts (incl. class 0)

// ---------------------------------------------------------------------------
// K1: per-batch class histogram of the support mask
// ---------------------------------------------------------------------------
__global__ void __launch_bounds__(256) hist_kernel(const int* __restrict__ masks) {
    __shared__ int h[K + 1];
    const int b   = blockIdx.x;
    const int tid = threadIdx.x;
    if (tid <= K) h[tid] = 0;
    __syncthreads();
    for (int p = tid; p < HW; p += 256) {
        int v = masks[b * HW + p];
        if (v >= 0 && v <= K) atomicAdd(&h[v], 1);   // guarded: never traps
    }
    __syncthreads();
    if (tid <= K) g_counts[b * (K + 1) + tid] = h[tid];
}

// ---------------------------------------------------------------------------
// K2: masked per-class sums.  One warp = one channel; lane-private smem slots
// acc[class][tid] (bank = tid%32 -> conflict-free dynamic indexing).
// 2 float4 loads in flight per lane to deepen MLP.  DRAM-bound (~128 MB).
// ---------------------------------------------------------------------------
__global__ void __launch_bounds__(256) proto_sum_kernel(
        const float* __restrict__ feat, const int* __restrict__ masks) {
    __shared__ unsigned char cls[HW];       // 4 KB
    __shared__ float acc[K][256];           // 16 KB

    const int b    = blockIdx.y;
    const int tid  = threadIdx.x;
    const int warp = tid >> 5;
    const int lane = tid & 31;
    const int c    = blockIdx.x * 8 + warp;

#pragma unroll
    for (int k = 0; k < K; k++) acc[k][tid] = 0.0f;
    for (int p = tid; p < HW; p += 256) {
        int v = masks[b * HW + p];
        cls[p] = (unsigned char)((v >= 1 && v <= K) ? v : 0);  // guarded
    }
    __syncthreads();

    const float4* f4 = (const float4*)(feat + ((size_t)b * C + c) * HW);
    const uchar4* c4 = (const uchar4*)cls;

    for (int i = lane; i < HW / 4; i += 64) {
        float4 v0 = f4[i];
        float4 v1 = f4[i + 32];
        uchar4 c0 = c4[i];
        uchar4 c1 = c4[i + 32];
        if (c0.x) acc[c0.x - 1][tid] += v0.x;
        if (c0.y) acc[c0.y - 1][tid] += v0.y;
        if (c0.z) acc[c0.z - 1][tid] += v0.z;
        if (c0.w) acc[c0.w - 1][tid] += v0.w;
        if (c1.x) acc[c1.x - 1][tid] += v1.x;
        if (c1.y) acc[c1.y - 1][tid] += v1.y;
        if (c1.z) acc[c1.z - 1][tid] += v1.z;
        if (c1.w) acc[c1.w - 1][tid] += v1.w;
    }

#pragma unroll
    for (int k = 0; k < K; k++) {
        float s = acc[k][tid];
#pragma unroll
        for (int off = 16; off; off >>= 1)
            s += __shfl_down_sync(0xffffffffu, s, off);
        if (lane == 0) g_num[((size_t)b * K + k) * C + c] = s;
    }
}

// ---------------------------------------------------------------------------
// K3: g_protoN = (num/count) / ||num/count||.
// argmax_k dot(protoN_k, q) == argmax_k cosine_sim.
// ---------------------------------------------------------------------------
__global__ void __launch_bounds__(256) finalize_kernel() {
    const int b = blockIdx.y, k = blockIdx.x, tid = threadIdx.x;
    const int cnt = g_counts[b * (K + 1) + k + 1];
    const float invCnt = cnt > 0 ? 1.0f / (float)cnt : 0.0f;
    const float* num = g_num    + ((size_t)(b * K + k)) * C;
    float*       out = g_protoN + ((size_t)(b * K + k)) * C;

    float pv[4];
    float ss = 0.0f;
#pragma unroll
    for (int j = 0; j < 4; j++) {
        pv[j] = num[tid + j * 256] * invCnt;
        ss += pv[j] * pv[j];
    }

    __shared__ float red[8];
    __shared__ float s_inv;
#pragma unroll
    for (int off = 16; off; off >>= 1)
        ss += __shfl_down_sync(0xffffffffu, ss, off);
    if ((tid & 31) == 0) red[tid >> 5] = ss;
    __syncthreads();
    if (tid == 0) {
        float s = 0.0f;
#pragma unroll
        for (int w = 0; w < 8; w++) s += red[w];
        s_inv = s > 0.0f ? 1.0f / sqrtf(s) : 0.0f;
    }
    __syncthreads();
    const float inv = s_inv;
#pragma unroll
    for (int j = 0; j < 4; j++) out[tid + j * 256] = pv[j] * inv;
}

// ---------------------------------------------------------------------------
// K4: MLP-deep match.  512 threads/CTA = 8 slices x 64 pixels; slice =
// (k_half, channel_quarter): each thread accumulates 8 protos over 256
// channels for 1 pixel, with a 16-channel LDG batch (2 KB in flight / warp
// -> ~4 TB/s DRAM ceiling vs 2 TB/s at 8 loads).  FFMA2 throughout.
// Cross-slice reduction in smem replicates R5's exact packed sum order.
// ---------------------------------------------------------------------------
__global__ void __launch_bounds__(512, 2) match_kernel(
        const float* __restrict__ q, float* __restrict__ out) {
    extern __shared__ __align__(16) char smem_raw[];
    float*              sp  = (float*)smem_raw;              // [K][C] = 64 KB
    unsigned long long* red = (unsigned long long*)smem_raw; // reuse: [64][16][4]

    const int b     = blockIdx.y;
    const int tid   = threadIdx.x;
    const int slice = tid >> 6;          // 0..7
    const int px    = tid & 63;          // 0..63
    const int kh    = slice & 1;         // k-half: protos [kh*8, kh*8+8)
    const int cq    = slice >> 1;        // channel quarter: [cq*256, cq*256+256)
    const int p     = blockIdx.x * 64 + px;

    // stage all 16x1024 normalized prototypes (L2-resident source, 512 KB)
    const float4* pr4 = (const float4*)(g_protoN + (size_t)b * K * C);
    for (int i = tid; i < K * C / 4; i += 512)
        ((float4*)sp)[i] = pr4[i];
    __syncthreads();

    const float* qb = q + ((size_t)b * C + cq * 256) * HW + p;

    unsigned long long acc2[8];
#pragma unroll
    for (int kk = 0; kk < 8; kk++) acc2[kk] = 0ull;

    for (int c = 0; c < 256; c += 16) {
        // 16 independent LDG.32 in flight (lanes = consecutive pixels)
        float qv[16];
#pragma unroll
        for (int j = 0; j < 16; j++)
            qv[j] = qb[(size_t)(c + j) * HW];
        unsigned long long qp[8];
#pragma unroll
        for (int j = 0; j < 8; j++)
            asm("mov.b64 %0, {%1, %2};" : "=l"(qp[j]) : "f"(qv[2*j]), "f"(qv[2*j+1]));

#pragma unroll
        for (int kk = 0; kk < 8; kk++) {
            const float* pb = &sp[(kh * 8 + kk) * C + cq * 256 + c];
            const ulonglong2 p0 = *(const ulonglong2*)(pb + 0);   // LDS.128 bcast
            const ulonglong2 p1 = *(const ulonglong2*)(pb + 4);
            const ulonglong2 p2 = *(const ulonglong2*)(pb + 8);
            const ulonglong2 p3 = *(const ulonglong2*)(pb + 12);
            asm("fma.rn.f32x2 %0, %1, %2, %0;" : "+l"(acc2[kk]) : "l"(qp[0]), "l"(p0.x));
            asm("fma.rn.f32x2 %0, %1, %2, %0;" : "+l"(acc2[kk]) : "l"(qp[1]), "l"(p0.y));
            asm("fma.rn.f32x2 %0, %1, %2, %0;" : "+l"(acc2[kk]) : "l"(qp[2]), "l"(p1.x));
            asm("fma.rn.f32x2 %0, %1, %2, %0;" : "+l"(acc2[kk]) : "l"(qp[3]), "l"(p1.y));
            asm("fma.rn.f32x2 %0, %1, %2, %0;" : "+l"(acc2[kk]) : "l"(qp[4]), "l"(p2.x));
            asm("fma.rn.f32x2 %0, %1, %2, %0;" : "+l"(acc2[kk]) : "l"(qp[5]), "l"(p2.y));
            asm("fma.rn.f32x2 %0, %1, %2, %0;" : "+l"(acc2[kk]) : "l"(qp[6]), "l"(p3.x));
            asm("fma.rn.f32x2 %0, %1, %2, %0;" : "+l"(acc2[kk]) : "l"(qp[7]), "l"(p3.y));
        }
    }

    // protos dead -> packed partials red[px][k][quarter]
    __syncthreads();
    {
        unsigned long long* dst = red + ((size_t)px * K + kh * 8) * 4 + cq;
#pragma unroll
        for (int kk = 0; kk < 8; kk++) dst[kk * 4] = acc2[kk];
    }
    __syncthreads();

    // quarter reduction (q0+q1)+(q2+q3) packed, fold lo+hi last (== R5 order),
    // then first-max-wins argmax (jnp.argmax tie semantics)
    if (tid < 64) {
        const unsigned long long* r = red + (size_t)tid * K * 4;
        float best = -3.0e38f;
        int   bi   = 0;
#pragma unroll
        for (int k = 0; k < K; k++) {
            unsigned long long s01, s23, s;
            asm("add.rn.f32x2 %0, %1, %2;" : "=l"(s01) : "l"(r[k*4+0]), "l"(r[k*4+1]));
            asm("add.rn.f32x2 %0, %1, %2;" : "=l"(s23) : "l"(r[k*4+2]), "l"(r[k*4+3]));
            asm("add.rn.f32x2 %0, %1, %2;" : "=l"(s)   : "l"(s01),      "l"(s23));
            float lo, hi;
            asm("mov.b64 {%0, %1}, %2;" : "=f"(lo), "=f"(hi) : "l"(s));
            const float v = lo + hi;
            if (v > best) { best = v; bi = k; }
        }
        out[(size_t)b * HW + blockIdx.x * 64 + tid] = (float)bi;  // f32 output
    }
}

// ---------------------------------------------------------------------------
extern "C" void kernel_launch(void* const* d_in, const int* in_sizes, int n_in,
                              void* d_out, int out_size) {
    // masks is the unique B*HW = 32768-element input; its position fixes the
    // ordering of the two feature tensors.
    int mask_idx = 1;
    for (int i = 0; i < n_in; i++)
        if (in_sizes[i] == B * HW) { mask_idx = i; break; }

    const int*   masks = (const int*)d_in[mask_idx];
    const float* sfeat;
    const float* qfeat;
    if (mask_idx == 1)      { sfeat = (const float*)d_in[0]; qfeat = (const float*)d_in[2]; }
    else if (mask_idx == 2) { qfeat = (const float*)d_in[0]; sfeat = (const float*)d_in[1]; }
    else                    { qfeat = (const float*)d_in[1]; sfeat = (const float*)d_in[2]; }
    float* out = (float*)d_out;
    (void)out_size;

    hist_kernel<<<B, 256>>>(masks);
    proto_sum_kernel<<<dim3(C / 8, B), 256>>>(sfeat, masks);
    finalize_kernel<<<dim3(K, B), 256>>>();

    static int smem_set = 0;
    if (!smem_set) {
        cudaFuncSetAttribute(match_kernel,
                             cudaFuncAttributeMaxDynamicSharedMemorySize,
                             K * C * (int)sizeof(float));
        smem_set = 1;
    }
    match_kernel<<<dim3(HW / 64, B), 512, K * C * sizeof(float)>>>(qfeat, out);
}